// round 4
// baseline (speedup 1.0000x reference)
#include <cuda_runtime.h>
#include <cuda_bf16.h>

// Batched 1D linear interpolation with clamped extrapolation.
// t: [B, N] sorted per row, v: [B, N], r: [B, M]  ->  out: [B, M]
//
// One CTA per row. Knots as interleaved (t,v) float2 pairs in SMEM.
// Per-row bucket table P[k] (ushort, KB uniform buckets over [tmin,tmax],
// sentinel P[KB]=NN) confines each query's searchsorted position to
// [P[k], P[k+1]] (expected width ~0.5 knots).
//
// Refinement = 3 FIXED branchless probe rounds (resolve width <= 4, which is
// ~99.98% of buckets for uniform data) + a rarely-entered warp-voted fallback
// loop that guarantees correctness for ANY sorted t.

#define NN 4096
#define MM 4096
#define KB 8063
#define TABLE (KB + 1)               // P[KB] = NN sentinel
#define THREADS 512
#define QPT (MM / THREADS)           // 8 queries per thread

__device__ __forceinline__ int bucket_of(float x, float tmin, float scale) {
    int k = (int)((x - tmin) * scale);   // monotone nondecreasing in x
    k = (k < 0) ? 0 : k;
    k = (k > KB - 1) ? KB - 1 : k;
    return k;
}

__global__ __launch_bounds__(THREADS, 3)
void interp1d_kernel(const float* __restrict__ t,
                     const float* __restrict__ v,
                     const float* __restrict__ r,
                     float* __restrict__ out) {
    __shared__ float2         tv[NN];     // 32768 B
    __shared__ unsigned short P[TABLE];   // 16128 B

    const int row = blockIdx.x;
    const float* trow = t + (size_t)row * NN;
    const float* vrow = v + (size_t)row * NN;
    const float* rrow = r + (size_t)row * MM;
    float*       orow = out + (size_t)row * MM;
    const int tid = threadIdx.x;

    // ---- Stage knot pairs ----
    const float4* t4 = reinterpret_cast<const float4*>(trow);
    const float4* v4 = reinterpret_cast<const float4*>(vrow);
    #pragma unroll
    for (int i = 0; i < NN / 4 / THREADS; i++) {       // 2 iterations
        int i4 = tid + i * THREADS;
        float4 a = t4[i4];
        float4 b = v4[i4];
        int base = i4 * 4;
        tv[base + 0] = make_float2(a.x, b.x);
        tv[base + 1] = make_float2(a.y, b.y);
        tv[base + 2] = make_float2(a.z, b.z);
        tv[base + 3] = make_float2(a.w, b.w);
    }
    // ---- Init table to NN via u32 stores (TABLE is even) ----
    unsigned int* P32 = reinterpret_cast<unsigned int*>(P);
    const unsigned int fill = ((unsigned)NN << 16) | (unsigned)NN;
    #pragma unroll
    for (int i = 0; i < (TABLE / 2 + THREADS - 1) / THREADS; i++) {
        int j = tid + i * THREADS;
        if (j < TABLE / 2) P32[j] = fill;
    }
    __syncthreads();

    const float tmin   = tv[0].x;
    const float tmax   = tv[NN - 1].x;
    const float vfirst = tv[0].y;
    const float vlast  = tv[NN - 1].y;
    const float span   = tmax - tmin;
    const float scale  = (span > 0.0f) ? (float)KB / span : 0.0f;

    // ---- Build: knot j owns table range (bucket(t[j-1]), bucket(t[j])] ----
    #pragma unroll
    for (int i = 0; i < NN / THREADS; i++) {           // 8 iterations
        int j = tid + i * THREADS;
        int bj = bucket_of(tv[j].x, tmin, scale);
        int bp = (j == 0) ? -1 : bucket_of(tv[j - 1].x, tmin, scale);
        for (int k = bp + 1; k <= bj; k++) P[k] = (unsigned short)j;
    }
    __syncthreads();

    // ---- Queries: 8 per thread, 4 register-interleaved at a time ----
    #pragma unroll
    for (int b = 0; b < QPT / 4; b++) {
        float rv[4];
        #pragma unroll
        for (int q = 0; q < 4; q++)
            rv[q] = rrow[tid + (b * 4 + q) * THREADS];  // coalesced

        int lo[4], hi[4];
        #pragma unroll
        for (int q = 0; q < 4; q++) {
            int k = bucket_of(rv[q], tmin, scale);
            lo[q] = P[k];
            hi[q] = P[k + 1];                            // sentinel-safe
        }

        // 3 fixed branchless refinement rounds (resolve width <= 4)
        #pragma unroll
        for (int rnd = 0; rnd < 3; rnd++) {
            #pragma unroll
            for (int q = 0; q < 4; q++) {
                int mid  = (lo[q] + hi[q]) >> 1;
                int midc = (mid < NN - 1) ? mid : NN - 1;
                float tm = tv[midc].x;
                bool go  = lo[q] < hi[q];
                bool le  = tm <= rv[q];
                lo[q] = (go &&  le) ? mid + 1 : lo[q];
                hi[q] = (go && !le) ? mid     : hi[q];
            }
        }

        // rare fallback for width > 4 (correct for any sorted t)
        int rem = (hi[0] - lo[0]) | (hi[1] - lo[1]) |
                  (hi[2] - lo[2]) | (hi[3] - lo[3]);
        while (__any_sync(0xffffffffu, rem != 0)) {
            #pragma unroll
            for (int q = 0; q < 4; q++) {
                int mid  = (lo[q] + hi[q]) >> 1;
                int midc = (mid < NN - 1) ? mid : NN - 1;
                float tm = tv[midc].x;
                bool go  = lo[q] < hi[q];
                bool le  = tm <= rv[q];
                lo[q] = (go &&  le) ? mid + 1 : lo[q];
                hi[q] = (go && !le) ? mid     : hi[q];
            }
            rem = (hi[0] - lo[0]) | (hi[1] - lo[1]) |
                  (hi[2] - lo[2]) | (hi[3] - lo[3]);
        }

        float res[4];
        #pragma unroll
        for (int q = 0; q < 4; q++) {
            int idx = lo[q];
            idx = (idx < 1) ? 1 : idx;
            idx = (idx > NN - 1) ? NN - 1 : idx;
            float2 p0 = tv[idx - 1];
            float2 p1 = tv[idx];
            float d = p1.x - p0.x;
            float denom = (d == 0.0f) ? 1.0f : d;
            float o = p0.y + (rv[q] - p0.x) * __fdividef(p1.y - p0.y, denom);
            o = (rv[q] < tmin) ? vfirst : o;   // clamped extrapolation
            o = (rv[q] > tmax) ? vlast  : o;
            res[q] = o;
        }

        #pragma unroll
        for (int q = 0; q < 4; q++)
            orow[tid + (b * 4 + q) * THREADS] = res[q];
    }
}

extern "C" void kernel_launch(void* const* d_in, const int* in_sizes, int n_in,
                              void* d_out, int out_size) {
    const float* t = (const float*)d_in[0];
    const float* v = (const float*)d_in[1];
    const float* r = (const float*)d_in[2];
    float* out = (float*)d_out;

    int B = in_sizes[0] / NN;   // 2048 for the reference shape
    interp1d_kernel<<<B, THREADS>>>(t, v, r, out);
}

// round 5
// speedup vs baseline: 1.1256x; 1.1256x over previous
#include <cuda_runtime.h>
#include <cuda_bf16.h>

// Batched 1D linear interpolation with clamped extrapolation.
// t: [B, N] sorted per row, v: [B, N], r: [B, M]  ->  out: [B, M]
//
// One CTA per row. Knots staged as SPLIT packed float arrays ts[]/vs[]
// (float2 interleaving made every random probe an 8-byte-strided LDS that
// camped on the 16 even banks -> 2x conflicts; split arrays use all 32).
// Per-row bucket table P[k] (ushort, KB uniform buckets, sentinel P[KB]=NN)
// confines searchsorted to [P[k], P[k+1]] (expected width ~0.5).
// Refinement: 3 fixed branchless rounds where RESOLVED lanes read ts[0]
// (broadcast, ~free) instead of a random address; then a rare warp-voted
// fallback loop guarantees correctness for any sorted t.

#define NN 4096
#define MM 4096
#define KB 8063
#define TABLE (KB + 1)               // P[KB] = NN sentinel
#define THREADS 512
#define QPT (MM / THREADS)           // 8 queries per thread

__device__ __forceinline__ int bucket_of(float x, float tmin, float scale) {
    int k = (int)((x - tmin) * scale);   // monotone nondecreasing in x
    k = (k < 0) ? 0 : k;
    k = (k > KB - 1) ? KB - 1 : k;
    return k;
}

__global__ __launch_bounds__(THREADS, 3)
void interp1d_kernel(const float* __restrict__ t,
                     const float* __restrict__ v,
                     const float* __restrict__ r,
                     float* __restrict__ out) {
    __shared__ float          ts[NN];     // 16384 B
    __shared__ float          vs[NN];     // 16384 B
    __shared__ unsigned short P[TABLE];   // 16128 B   (total 48896 <= 48KB static)

    const int row = blockIdx.x;
    const float* trow = t + (size_t)row * NN;
    const float* vrow = v + (size_t)row * NN;
    const float* rrow = r + (size_t)row * MM;
    float*       orow = out + (size_t)row * MM;
    const int tid = threadIdx.x;

    // ---- Stage knots (float4 LDG -> STS.128, conflict-free) ----
    const float4* t4 = reinterpret_cast<const float4*>(trow);
    const float4* v4 = reinterpret_cast<const float4*>(vrow);
    float4* ts4 = reinterpret_cast<float4*>(ts);
    float4* vs4 = reinterpret_cast<float4*>(vs);
    #pragma unroll
    for (int i = 0; i < NN / 4 / THREADS; i++) {       // 2 iterations
        int i4 = tid + i * THREADS;
        ts4[i4] = t4[i4];
        vs4[i4] = v4[i4];
    }
    // ---- Init table to NN via u32 stores (TABLE is even) ----
    unsigned int* P32 = reinterpret_cast<unsigned int*>(P);
    const unsigned int fill = ((unsigned)NN << 16) | (unsigned)NN;
    #pragma unroll
    for (int i = 0; i < (TABLE / 2 + THREADS - 1) / THREADS; i++) {
        int j = tid + i * THREADS;
        if (j < TABLE / 2) P32[j] = fill;
    }
    __syncthreads();

    const float tmin   = ts[0];
    const float tmax   = ts[NN - 1];
    const float vfirst = vs[0];
    const float vlast  = vs[NN - 1];
    const float span   = tmax - tmin;
    const float scale  = (span > 0.0f) ? (float)KB / span : 0.0f;

    // ---- Build: knot j owns table range (bucket(t[j-1]), bucket(t[j])] ----
    #pragma unroll
    for (int i = 0; i < NN / THREADS; i++) {           // 8 iterations
        int j = tid + i * THREADS;
        int bj = bucket_of(ts[j], tmin, scale);
        int bp = (j == 0) ? -1 : bucket_of(ts[j - 1], tmin, scale);
        for (int k = bp + 1; k <= bj; k++) P[k] = (unsigned short)j;
    }
    __syncthreads();

    // ---- Queries: 8 per thread, 4 register-interleaved at a time ----
    #pragma unroll
    for (int b = 0; b < QPT / 4; b++) {
        float rv[4];
        #pragma unroll
        for (int q = 0; q < 4; q++)
            rv[q] = rrow[tid + (b * 4 + q) * THREADS];  // coalesced

        int lo[4], hi[4];
        #pragma unroll
        for (int q = 0; q < 4; q++) {
            int k = bucket_of(rv[q], tmin, scale);
            lo[q] = P[k];
            hi[q] = P[k + 1];                            // sentinel-safe
        }

        // 3 fixed branchless rounds; resolved lanes park on ts[0] (broadcast)
        #pragma unroll
        for (int rnd = 0; rnd < 3; rnd++) {
            #pragma unroll
            for (int q = 0; q < 4; q++) {
                bool go  = lo[q] < hi[q];
                int mid  = (lo[q] + hi[q]) >> 1;
                int addr = go ? mid : 0;                 // broadcast when done
                float tm = ts[addr];
                bool le  = tm <= rv[q];
                lo[q] = (go &&  le) ? mid + 1 : lo[q];
                hi[q] = (go && !le) ? mid     : hi[q];
            }
        }

        // rare fallback for width > 4 (correct for any sorted t)
        int rem = (hi[0] - lo[0]) | (hi[1] - lo[1]) |
                  (hi[2] - lo[2]) | (hi[3] - lo[3]);
        while (__any_sync(0xffffffffu, rem != 0)) {
            #pragma unroll
            for (int q = 0; q < 4; q++) {
                bool go  = lo[q] < hi[q];
                int mid  = (lo[q] + hi[q]) >> 1;
                int addr = go ? mid : 0;
                float tm = ts[addr];
                bool le  = tm <= rv[q];
                lo[q] = (go &&  le) ? mid + 1 : lo[q];
                hi[q] = (go && !le) ? mid     : hi[q];
            }
            rem = (hi[0] - lo[0]) | (hi[1] - lo[1]) |
                  (hi[2] - lo[2]) | (hi[3] - lo[3]);
        }

        float res[4];
        #pragma unroll
        for (int q = 0; q < 4; q++) {
            int idx = lo[q];
            idx = (idx < 1) ? 1 : idx;
            idx = (idx > NN - 1) ? NN - 1 : idx;
            float t0 = ts[idx - 1];
            float t1 = ts[idx];
            float v0 = vs[idx - 1];
            float v1 = vs[idx];
            float d = t1 - t0;
            float denom = (d == 0.0f) ? 1.0f : d;
            float o = v0 + (rv[q] - t0) * __fdividef(v1 - v0, denom);
            o = (rv[q] < tmin) ? vfirst : o;   // clamped extrapolation
            o = (rv[q] > tmax) ? vlast  : o;
            res[q] = o;
        }

        #pragma unroll
        for (int q = 0; q < 4; q++)
            orow[tid + (b * 4 + q) * THREADS] = res[q];
    }
}

extern "C" void kernel_launch(void* const* d_in, const int* in_sizes, int n_in,
                              void* d_out, int out_size) {
    const float* t = (const float*)d_in[0];
    const float* v = (const float*)d_in[1];
    const float* r = (const float*)d_in[2];
    float* out = (float*)d_out;

    int B = in_sizes[0] / NN;   // 2048 for the reference shape
    interp1d_kernel<<<B, THREADS>>>(t, v, r, out);
}